// round 4
// baseline (speedup 1.0000x reference)
#include <cuda_runtime.h>
#include <cuda_fp16.h>

#define S  50000
#define E  20000
#define K  128
#define B  16384
#define NE 1000000

// ---------------- static device scratch ------------------------------------
__device__ float  g_statA[S * K];
__device__ float  g_statB[S * K];
__device__ float  g_kdA[E * K];
__device__ float  g_kdB[E * K];
__device__ __half g_sembH[S * K];
__device__ __half g_eembH[E * K];
__device__ __half g_statAH[S * K];
__device__ __half g_kdAH[E * K];
// merged CSRs: S-keyed (gathers exercise-side rows), E-keyed (gathers student-side)
__device__ int    g_rpS[S + 1];
__device__ int    g_rpE[E + 1];
__device__ int    g_curS[S];
__device__ int    g_curE[E];
__device__ int2   g_edgeS[2 * NE];   // (src_col, val_bits) sorted by dest student
__device__ int2   g_edgeE[2 * NE];   // (src_col, val_bits) sorted by dest exercise
__device__ unsigned char g_needS[S];   // zero-init at load; self-clearing
__device__ unsigned char g_needE[E];
__device__ int    g_list[2 * B];
__device__ int    g_cnt;

__device__ __forceinline__ float sigm(float x) {
    return 1.0f / (1.0f + __expf(-x));
}

// ---------------- setup: zero rowptrs + fp16 conversion (fused) -------------
__global__ void k_setup(const float* __restrict__ semb, const float* __restrict__ eemb) {
    int i = blockIdx.x * blockDim.x + threadIdx.x;
    if (i < S + 1) g_rpS[i] = 0;
    if (i < E + 1) g_rpE[i] = 0;
    const int nS = S * K / 2, nE = E * K / 2;
    if (i < nS) {
        float2 f = ((const float2*)semb)[i];
        ((__half2*)g_sembH)[i] = __floats2half2_rn(f.x, f.y);
    } else if (i < nS + nE) {
        int j = i - nS;
        float2 f = ((const float2*)eemb)[j];
        ((__half2*)g_eembH)[j] = __floats2half2_rn(f.x, f.y);
    }
}

__global__ void k_flags(const int* __restrict__ stu_id, const int* __restrict__ exid) {
    int q = blockIdx.x * blockDim.x + threadIdx.x;
    if (q == 0) g_cnt = 0;
    if (q >= B) return;
    g_needS[stu_id[q]] = 1;   // benign races
    g_needE[exid[q]]   = 1;
}

__global__ void k_compact() {
    int i = blockIdx.x * blockDim.x + threadIdx.x;
    if (i < S) {
        if (g_needS[i]) { g_needS[i] = 0; int p = atomicAdd(&g_cnt, 1); g_list[p] = i; }
    } else if (i < S + E) {
        int j = i - S;
        if (g_needE[j]) { g_needE[j] = 0; int p = atomicAdd(&g_cnt, 1); g_list[p] = j | (1 << 30); }
    }
}

// ---------------- CSR build ------------------------------------------------
__global__ void k_hist(const int* __restrict__ r1, const int* __restrict__ r0,
                       const int* __restrict__ c1, const int* __restrict__ c0) {
    int e = blockIdx.x * blockDim.x + threadIdx.x;
    if (e >= NE) return;
    atomicAdd(&g_rpS[r1[e]], 1);
    atomicAdd(&g_rpS[r0[e]], 1);
    atomicAdd(&g_rpE[c1[e]], 1);
    atomicAdd(&g_rpE[c0[e]], 1);
}

// one block per CSR: exclusive scan of counts -> rowptr + cursor copy
__global__ void k_scan() {
    int o = blockIdx.x;
    int N = (o == 0) ? S : E;
    int* cnt = (o == 0) ? g_rpS : g_rpE;
    int* cur = (o == 0) ? g_curS : g_curE;
    __shared__ int wsum[32];
    __shared__ int srun;
    int tid = threadIdx.x;
    int lane = tid & 31, wid = tid >> 5;
    if (tid == 0) srun = 0;
    __syncthreads();
    int ntiles = (N + 1023) >> 10;
    for (int t = 0; t < ntiles; ++t) {
        int i = (t << 10) + tid;
        int v = (i < N) ? cnt[i] : 0;
        int incl = v;
        #pragma unroll
        for (int d = 1; d < 32; d <<= 1) {
            int n = __shfl_up_sync(0xffffffffu, incl, d);
            if (lane >= d) incl += n;
        }
        if (lane == 31) wsum[wid] = incl;
        __syncthreads();
        if (wid == 0) {
            int ws = wsum[lane];
            int wincl = ws;
            #pragma unroll
            for (int d = 1; d < 32; d <<= 1) {
                int n = __shfl_up_sync(0xffffffffu, wincl, d);
                if (lane >= d) wincl += n;
            }
            wsum[lane] = wincl - ws;
        }
        __syncthreads();
        int run = srun;
        int excl = run + wsum[wid] + incl - v;
        if (i < N) { cnt[i] = excl; cur[i] = excl; }
        __syncthreads();
        if (tid == 1023) srun = excl + v;
        __syncthreads();
    }
    if (tid == 0) cnt[N] = srun;
}

__global__ void k_scatter(const int* __restrict__ r1, const int* __restrict__ r0,
                          const int* __restrict__ c1, const int* __restrict__ c0,
                          const float* __restrict__ vui1, const float* __restrict__ vui0,
                          const float* __restrict__ viu1, const float* __restrict__ viu0) {
    int e = blockIdx.x * blockDim.x + threadIdx.x;
    if (e >= NE) return;
    int a = r1[e], b = r0[e], c = c1[e], d = c0[e];
    int p;
    p = atomicAdd(&g_curS[a], 1); g_edgeS[p] = make_int2(c, __float_as_int(vui1[e]));
    p = atomicAdd(&g_curS[b], 1); g_edgeS[p] = make_int2(d, __float_as_int(vui0[e]));
    p = atomicAdd(&g_curE[c], 1); g_edgeE[p] = make_int2(a, __float_as_int(viu1[e]));
    p = atomicAdd(&g_curE[d], 1); g_edgeE[p] = make_int2(b, __float_as_int(viu0[e]));
}

// ---------------- SpMM core (warp per dest row, unroll-8 batched loads) -----
__device__ __forceinline__ void acc_h(uint2 r, float v,
                                      float& ax, float& ay, float& az, float& aw) {
    __half2 h0 = *reinterpret_cast<__half2*>(&r.x);
    __half2 h1 = *reinterpret_cast<__half2*>(&r.y);
    float2 f0 = __half22float2(h0);
    float2 f1 = __half22float2(h1);
    ax += v * f0.x; ay += v * f0.y; az += v * f1.x; aw += v * f1.y;
}

__device__ __forceinline__ void gather_run(const int2* __restrict__ ed,
                                           int e, int end, int lane,
                                           const uint2* __restrict__ XH,
                                           float& ax, float& ay, float& az, float& aw) {
    for (; e + 8 <= end; e += 8) {
        int2 m[8];
        uint2 r[8];
        #pragma unroll
        for (int i = 0; i < 8; ++i) m[i] = ed[e + i];
        #pragma unroll
        for (int i = 0; i < 8; ++i) r[i] = XH[(size_t)m[i].x * 32 + lane];
        #pragma unroll
        for (int i = 0; i < 8; ++i)
            acc_h(r[i], __int_as_float(m[i].y), ax, ay, az, aw);
    }
    // tail (<=7)
    int rem = end - e;
    if (rem > 0) {
        int2 m[7];
        uint2 r[7];
        #pragma unroll
        for (int i = 0; i < 7; ++i) if (i < rem) m[i] = ed[e + i];
        #pragma unroll
        for (int i = 0; i < 7; ++i) if (i < rem) r[i] = XH[(size_t)m[i].x * 32 + lane];
        #pragma unroll
        for (int i = 0; i < 7; ++i) if (i < rem)
            acc_h(r[i], __int_as_float(m[i].y), ax, ay, az, aw);
    }
}

// layer 1: full S+E rows, writes fp32 result + fp16 gather copy
__global__ void k_spmm1(const float* __restrict__ semb, const float* __restrict__ eemb,
                        const float* __restrict__ di1, const float* __restrict__ di0,
                        const float* __restrict__ dj1, const float* __restrict__ dj0) {
    int w = (blockIdx.x * (int)blockDim.x + threadIdx.x) >> 5;
    int lane = threadIdx.x & 31;
    if (w >= S + E) return;
    int row;
    const int2*  ed;
    const int*   rp;
    const uint2* XH;
    const float* selfin;
    float d;
    float*  outF;
    __half* outH;
    if (w < S) {
        row = w; ed = g_edgeS; rp = g_rpS; XH = (const uint2*)g_eembH;
        selfin = semb; d = di1[row] + di0[row]; outF = g_statA; outH = g_statAH;
    } else {
        row = w - S; ed = g_edgeE; rp = g_rpE; XH = (const uint2*)g_sembH;
        selfin = eemb; d = dj1[row] + dj0[row]; outF = g_kdA; outH = g_kdAH;
    }
    float4 sv = ((const float4*)selfin)[(size_t)row * 32 + lane];
    float ax = sv.x * d, ay = sv.y * d, az = sv.z * d, aw = sv.w * d;
    gather_run(ed, rp[row], rp[row + 1], lane, XH, ax, ay, az, aw);
    float4 r; r.x = ax; r.y = ay; r.z = az; r.w = aw;
    ((float4*)outF)[(size_t)row * 32 + lane] = r;
    __half2 h0 = __floats2half2_rn(ax, ay);
    __half2 h1 = __floats2half2_rn(az, aw);
    uint2 hw; hw.x = *(unsigned int*)&h0; hw.y = *(unsigned int*)&h1;
    ((uint2*)outH)[(size_t)row * 32 + lane] = hw;
}

// layer 2: only rows needed by the MLP (work list), fp32 output only
__global__ void k_spmm2(const float* __restrict__ di1, const float* __restrict__ di0,
                        const float* __restrict__ dj1, const float* __restrict__ dj0) {
    int idx = (blockIdx.x * (int)blockDim.x + threadIdx.x) >> 5;
    int lane = threadIdx.x & 31;
    if (idx >= g_cnt) return;
    int enc = g_list[idx];
    int row = enc & 0x3FFFFFFF;
    const int2*  ed;
    const int*   rp;
    const uint2* XH;
    const float* selfin;
    float d;
    float* outF;
    if (enc & (1 << 30)) {   // kdiff row: gathers layer-1 stat
        ed = g_edgeE; rp = g_rpE; XH = (const uint2*)g_statAH;
        selfin = g_kdA; d = dj1[row] + dj0[row]; outF = g_kdB;
    } else {                 // stat row: gathers layer-1 kdiff
        ed = g_edgeS; rp = g_rpS; XH = (const uint2*)g_kdAH;
        selfin = g_statA; d = di1[row] + di0[row]; outF = g_statB;
    }
    float4 sv = ((const float4*)selfin)[(size_t)row * 32 + lane];
    float ax = sv.x * d, ay = sv.y * d, az = sv.z * d, aw = sv.w * d;
    gather_run(ed, rp[row], rp[row + 1], lane, XH, ax, ay, az, aw);
    float4 r; r.x = ax; r.y = ay; r.z = az; r.w = aw;
    ((float4*)outF)[(size_t)row * 32 + lane] = r;
}

// ---------------- fused MLP head (16 queries per 256-thread block) ---------
__global__ void k_mlp(const int* __restrict__ stu_id, const int* __restrict__ exid,
                      const float* __restrict__ ikp,
                      const float* __restrict__ sbias, const float* __restrict__ edisc,
                      const float* __restrict__ W1, const float* __restrict__ b1,
                      const float* __restrict__ W2, const float* __restrict__ b2,
                      const float* __restrict__ W3, const float* __restrict__ b3,
                      float* __restrict__ outp) {
    __shared__ float xs[16 * 128];
    __shared__ float h1s[16 * 256];
    int tid = threadIdx.x;
    int qbase = blockIdx.x * 16;

    for (int idx = tid; idx < 16 * 128; idx += 256) {
        int r = idx >> 7, k = idx & 127;
        int q = qbase + r;
        int st = stu_id[q], ex = exid[q];
        float a  = sigm(g_statB[(size_t)st * 128 + k] + sbias[st]);
        float bk = sigm(g_kdB[(size_t)ex * 128 + k]);
        float ed = sigm(edisc[ex]);
        xs[idx] = ikp[(size_t)q * 128 + k] * (a - bk) * ed;
    }
    __syncthreads();

    {
        float acc[16];
        #pragma unroll
        for (int r = 0; r < 16; ++r) acc[r] = 0.f;
        const float* wrow = W1 + (size_t)tid * 128;
        for (int k = 0; k < 128; ++k) {
            float w = fabsf(wrow[k]);
            #pragma unroll
            for (int r = 0; r < 16; ++r) acc[r] += w * xs[r * 128 + k];
        }
        float bb = b1[tid];
        #pragma unroll
        for (int r = 0; r < 16; ++r) h1s[r * 256 + tid] = tanhf(acc[r] + bb);
    }
    __syncthreads();

    {
        int j = tid & 127;
        int rb = (tid >> 7) * 8;
        float acc[8];
        #pragma unroll
        for (int r = 0; r < 8; ++r) acc[r] = 0.f;
        const float* wrow = W2 + (size_t)j * 256;
        for (int k = 0; k < 256; ++k) {
            float w = fabsf(wrow[k]);
            #pragma unroll
            for (int r = 0; r < 8; ++r) acc[r] += w * h1s[(rb + r) * 256 + k];
        }
        float bb = b2[j];
        #pragma unroll
        for (int r = 0; r < 8; ++r) xs[(rb + r) * 128 + j] = tanhf(acc[r] + bb);
    }
    __syncthreads();

    {
        int wid = tid >> 5, lane = tid & 31;
        #pragma unroll
        for (int rr = 0; rr < 2; ++rr) {
            int r = wid * 2 + rr;
            float s = 0.f;
            #pragma unroll
            for (int k = lane; k < 128; k += 32) s += fabsf(W3[k]) * xs[r * 128 + k];
            #pragma unroll
            for (int d = 16; d; d >>= 1) s += __shfl_xor_sync(0xffffffffu, s, d);
            if (lane == 0) outp[qbase + r] = sigm(s + b3[0]);
        }
    }
}

// ---------------- launch ----------------------------------------------------
extern "C" void kernel_launch(void* const* d_in, const int* in_sizes, int n_in,
                              void* d_out, int out_size) {
    const int*   stu_id = (const int*)d_in[0];
    const int*   exid   = (const int*)d_in[1];
    const float* ikp    = (const float*)d_in[2];
    const int*   rows1  = (const int*)d_in[3];
    const int*   cols1  = (const int*)d_in[4];
    const int*   rows0  = (const int*)d_in[5];
    const int*   cols0  = (const int*)d_in[6];
    const float* vui1   = (const float*)d_in[7];
    const float* viu1   = (const float*)d_in[8];
    const float* vui0   = (const float*)d_in[9];
    const float* viu0   = (const float*)d_in[10];
    const float* di1    = (const float*)d_in[11];
    const float* dj1    = (const float*)d_in[12];
    const float* di0    = (const float*)d_in[13];
    const float* dj0    = (const float*)d_in[14];
    const float* semb   = (const float*)d_in[15];
    const float* eemb   = (const float*)d_in[16];
    const float* sbias  = (const float*)d_in[17];
    const float* edisc  = (const float*)d_in[18];
    const float* W1     = (const float*)d_in[19];
    const float* b1     = (const float*)d_in[20];
    const float* W2     = (const float*)d_in[21];
    const float* b2     = (const float*)d_in[22];
    const float* W3     = (const float*)d_in[23];
    const float* b3     = (const float*)d_in[24];
    float* outp = (float*)d_out;

    k_setup<<<((S + E) * K / 2 + 255) / 256, 256>>>(semb, eemb);
    k_flags<<<(B + 255) / 256, 256>>>(stu_id, exid);
    k_compact<<<(S + E + 255) / 256, 256>>>();
    k_hist<<<(NE + 255) / 256, 256>>>(rows1, rows0, cols1, cols0);
    k_scan<<<2, 1024>>>();
    k_scatter<<<(NE + 255) / 256, 256>>>(rows1, rows0, cols1, cols0,
                                         vui1, vui0, viu1, viu0);

    // layer 1 (full) + layer 2 (dest-filtered)
    k_spmm1<<<((S + E) * 32 + 255) / 256, 256>>>(semb, eemb, di1, di0, dj1, dj0);
    k_spmm2<<<(2 * B * 32 + 255) / 256, 256>>>(di1, di0, dj1, dj0);

    k_mlp<<<B / 16, 256>>>(stu_id, exid, ikp, sbias, edisc,
                           W1, b1, W2, b2, W3, b3, outp);
}